// round 7
// baseline (speedup 1.0000x reference)
#include <cuda_runtime.h>
#include <cuda_fp16.h>
#include <math_constants.h>
#include <cstdint>

// Problem constants
#define MAXN 100000
#define MAXE 1600000
#define D 128
#define DOUT 47
#define BN_EPS 1e-5f

// Scratch (device globals; allocation-free per harness rules)
__device__ __half g_A[(size_t)MAXN * D];  // GEMM output (dinv-prescaled), fp16, gathered
__device__ float  g_C[(size_t)MAXN * D];  // h1 (post BN+ReLU), fp32
__device__ float  g_dinv[MAXN];           // 1/sqrt(deg)
__device__ float  g_bn_s[D];              // fused BN scale
__device__ float  g_bn_t[D];              // fused BN bias
__device__ int    g_cnt[MAXN];            // dst histogram (edges only)
__device__ int    g_off[MAXN];            // exclusive prefix of g_cnt
__device__ int    g_cursor[MAXN];         // scatter cursors
__device__ int    g_es[MAXE];             // src ids, sorted by dst
__device__ int    g_bsum[64];             // scan block sums
__device__ int    g_is64;                 // edge_index dtype flag

// ---------------------------------------------------------------------------
// Edge-index dtype detection + accessor (int64 vs silently-downcast int32).
// ---------------------------------------------------------------------------
__global__ void detect_dtype(const unsigned int* __restrict__ ei32, int e) {
    if (blockIdx.x == 0 && threadIdx.x == 0) {
        int is64 = 1;
        int lim = (e < 64) ? e : 64;
        for (int i = 0; i < lim; i++) {
            if (ei32[2 * i + 1] != 0u) { is64 = 0; break; }
        }
        g_is64 = is64;
    }
}

__device__ __forceinline__ int load_idx(const void* __restrict__ ei, int e,
                                        int which, int i) {
    if (g_is64) {
        const long long* p = (const long long*)ei;
        return (int)p[(size_t)which * e + i];
    } else {
        const int* p = (const int*)ei;
        return p[(size_t)which * e + i];
    }
}

// ---------------------------------------------------------------------------
// Counting sort by dst: histogram -> scan -> scatter ; degrees ; BN prep
// ---------------------------------------------------------------------------
__global__ void cnt_zero(int n) {
    int i = blockIdx.x * blockDim.x + threadIdx.x;
    if (i < n) g_cnt[i] = 0;
}

__global__ void cnt_count(const void* __restrict__ ei, int e) {
    int i = blockIdx.x * blockDim.x + threadIdx.x;
    if (i < e) atomicAdd(&g_cnt[load_idx(ei, e, 1, i)], 1);
}

__global__ __launch_bounds__(256) void scan1(int n) {
    __shared__ int warp_sums[8];
    int tid = threadIdx.x;
    int base = blockIdx.x * 2048 + tid * 8;
    int v[8];
    int tot = 0;
#pragma unroll
    for (int i = 0; i < 8; i++) {
        int idx = base + i;
        v[i] = (idx < n) ? g_cnt[idx] : 0;
        tot += v[i];
    }
    int lane = tid & 31, wid = tid >> 5;
    int x = tot;
#pragma unroll
    for (int o = 1; o < 32; o <<= 1) {
        int y = __shfl_up_sync(0xFFFFFFFFu, x, o);
        if (lane >= o) x += y;
    }
    if (lane == 31) warp_sums[wid] = x;
    __syncthreads();
    if (wid == 0) {
        int w = (lane < 8) ? warp_sums[lane] : 0;
#pragma unroll
        for (int o = 1; o < 8; o <<= 1) {
            int y = __shfl_up_sync(0xFFFFFFFFu, w, o);
            if (lane >= o && lane < 8) w += y;
        }
        if (lane < 8) warp_sums[lane] = w;
    }
    __syncthreads();
    int excl = x - tot + ((wid > 0) ? warp_sums[wid - 1] : 0);
    int run = excl;
#pragma unroll
    for (int i = 0; i < 8; i++) {
        int idx = base + i;
        if (idx < n) g_off[idx] = run;
        run += v[i];
    }
    if (tid == 255) g_bsum[blockIdx.x] = excl + tot;
}

__global__ void scan2(int nb) {
    if (threadIdx.x == 0 && blockIdx.x == 0) {
        int run = 0;
        for (int i = 0; i < nb; i++) {
            int t = g_bsum[i];
            g_bsum[i] = run;
            run += t;
        }
    }
}

__global__ void scan3(int n) {
    int i = blockIdx.x * blockDim.x + threadIdx.x;
    if (i < n) {
        int o = g_off[i] + g_bsum[i >> 11];
        g_off[i]    = o;
        g_cursor[i] = o;
        g_dinv[i]   = rsqrtf((float)(g_cnt[i] + 1));   // +1 self-loop
    }
}

__global__ void scatter(const void* __restrict__ ei, int e) {
    int i = blockIdx.x * blockDim.x + threadIdx.x;
    if (i < e) {
        int s = load_idx(ei, e, 0, i);
        int d = load_idx(ei, e, 1, i);
        int p = atomicAdd(&g_cursor[d], 1);
        g_es[p] = s;
    }
}

__global__ void bn_prep(const float* __restrict__ b1, const float* __restrict__ gamma,
                        const float* __restrict__ beta, const float* __restrict__ mean,
                        const float* __restrict__ var) {
    int i = threadIdx.x;
    if (i < D) {
        float rs = rsqrtf(var[i] + BN_EPS);
        float s = rs * gamma[i];
        g_bn_s[i] = s;
        g_bn_t[i] = (b1[i] - mean[i]) * s + beta[i];
    }
}

// ---------------------------------------------------------------------------
// Tensor-core GEMM via mma.sync m16n8k16 (fp16 in, fp32 accum), hi/lo split:
//   X @ W  ≈ Xhi·Whi + Xlo·Whi + Xhi·Wlo      (lo·lo term ~2^-22, dropped)
// g_A = fp16((X @ W) * dinv[row]).
// layer==0: X = x_in ; layer==1: X = g_C.
// CTA: 128 rows x 128 cols x K=128; 8 warps, warp tile 32(M) x 64(N).
// ---------------------------------------------------------------------------
#define SP 136   // smem row stride in halves (128 + 8 pad -> conflict-free frags)

__device__ __forceinline__ void mma16816(float* c, const uint32_t* a,
                                         const uint32_t* b) {
    asm volatile(
        "mma.sync.aligned.m16n8k16.row.col.f32.f16.f16.f32 "
        "{%0,%1,%2,%3}, {%4,%5,%6,%7}, {%8,%9}, {%0,%1,%2,%3};"
        : "+f"(c[0]), "+f"(c[1]), "+f"(c[2]), "+f"(c[3])
        : "r"(a[0]), "r"(a[1]), "r"(a[2]), "r"(a[3]), "r"(b[0]), "r"(b[1]));
}

__global__ __launch_bounds__(256) void gemm_mma(const float* __restrict__ x_in,
                                                const float* __restrict__ W,
                                                int layer, int n) {
    extern __shared__ __half sm[];
    __half* sAhi = sm;                 // [128][SP]
    __half* sAlo = sm + 128 * SP;
    __half* sBhi = sm + 2 * 128 * SP;  // [n][k] transposed W
    __half* sBlo = sm + 3 * 128 * SP;

    const float* __restrict__ X = (layer == 0) ? x_in : g_C;

    int tid = threadIdx.x;
    int blockM = blockIdx.x * 128;

    // ---- Load A tile: 128x128 fp32 -> hi/lo fp16 (row-major, padded) ----
    for (int idx = tid; idx < 128 * 32; idx += 256) {
        int row = idx >> 5;
        int col = (idx & 31) * 4;
        int gr = blockM + row;
        float4 v = make_float4(0.f, 0.f, 0.f, 0.f);
        if (gr < n) v = *(const float4*)&X[(size_t)gr * D + col];
        __half h0 = __float2half_rn(v.x), h1 = __float2half_rn(v.y);
        __half h2 = __float2half_rn(v.z), h3 = __float2half_rn(v.w);
        __half2 hi01; hi01.x = h0; hi01.y = h1;
        __half2 hi23; hi23.x = h2; hi23.y = h3;
        *(__half2*)&sAhi[row * SP + col]     = hi01;
        *(__half2*)&sAhi[row * SP + col + 2] = hi23;
        __half2 lo01, lo23;
        lo01.x = __float2half_rn(v.x - __half2float(h0));
        lo01.y = __float2half_rn(v.y - __half2float(h1));
        lo23.x = __float2half_rn(v.z - __half2float(h2));
        lo23.y = __float2half_rn(v.w - __half2float(h3));
        *(__half2*)&sAlo[row * SP + col]     = lo01;
        *(__half2*)&sAlo[row * SP + col + 2] = lo23;
    }

    // ---- Load W (k-major [k][n]) -> transposed hi/lo [n][k] ----
    for (int idx = tid; idx < 128 * 32; idx += 256) {
        int k = idx >> 5;
        int nn = (idx & 31) * 4;
        float4 v = *(const float4*)&W[(size_t)k * D + nn];
        float f[4] = {v.x, v.y, v.z, v.w};
#pragma unroll
        for (int j = 0; j < 4; j++) {
            __half h = __float2half_rn(f[j]);
            sBhi[(nn + j) * SP + k] = h;
            sBlo[(nn + j) * SP + k] = __float2half_rn(f[j] - __half2float(h));
        }
    }
    __syncthreads();

    // ---- MMA mainloop ----
    int wid  = tid >> 5;
    int lane = tid & 31;
    int warpM = (wid & 3) * 32;   // 4 warps down M
    int warpN = (wid >> 2) * 64;  // 2 warps across N
    int qr = lane >> 2;           // 0..7
    int qc = lane & 3;            // 0..3

    float acc[2][8][4];
#pragma unroll
    for (int mt = 0; mt < 2; mt++)
#pragma unroll
        for (int nt = 0; nt < 8; nt++)
#pragma unroll
            for (int j = 0; j < 4; j++) acc[mt][nt][j] = 0.f;

#pragma unroll
    for (int ks = 0; ks < 8; ks++) {
        int kb = ks * 16;
        uint32_t ahi[2][4], alo[2][4];
#pragma unroll
        for (int mt = 0; mt < 2; mt++) {
            int r0 = warpM + mt * 16 + qr;
            const __half* pHi = &sAhi[r0 * SP + kb + qc * 2];
            const __half* pLo = &sAlo[r0 * SP + kb + qc * 2];
            ahi[mt][0] = *(const uint32_t*)pHi;
            ahi[mt][1] = *(const uint32_t*)(pHi + 8 * SP);
            ahi[mt][2] = *(const uint32_t*)(pHi + 8);
            ahi[mt][3] = *(const uint32_t*)(pHi + 8 * SP + 8);
            alo[mt][0] = *(const uint32_t*)pLo;
            alo[mt][1] = *(const uint32_t*)(pLo + 8 * SP);
            alo[mt][2] = *(const uint32_t*)(pLo + 8);
            alo[mt][3] = *(const uint32_t*)(pLo + 8 * SP + 8);
        }
#pragma unroll
        for (int nt = 0; nt < 8; nt++) {
            int nb = warpN + nt * 8 + qr;
            const __half* pBh = &sBhi[nb * SP + kb + qc * 2];
            const __half* pBl = &sBlo[nb * SP + kb + qc * 2];
            uint32_t bhi[2], blo[2];
            bhi[0] = *(const uint32_t*)pBh;
            bhi[1] = *(const uint32_t*)(pBh + 8);
            blo[0] = *(const uint32_t*)pBl;
            blo[1] = *(const uint32_t*)(pBl + 8);
#pragma unroll
            for (int mt = 0; mt < 2; mt++) {
                mma16816(acc[mt][nt], ahi[mt], bhi);
                mma16816(acc[mt][nt], alo[mt], bhi);
                mma16816(acc[mt][nt], ahi[mt], blo);
            }
        }
    }

    // ---- Epilogue: scale by dinv[row], convert to fp16, store g_A ----
#pragma unroll
    for (int mt = 0; mt < 2; mt++) {
        int r0 = blockM + warpM + mt * 16 + qr;
        int r1 = r0 + 8;
        float d0 = (r0 < n) ? g_dinv[r0] : 0.f;
        float d1 = (r1 < n) ? g_dinv[r1] : 0.f;
#pragma unroll
        for (int nt = 0; nt < 8; nt++) {
            int col = warpN + nt * 8 + qc * 2;
            if (r0 < n) {
                __half2 h = __floats2half2_rn(acc[mt][nt][0] * d0,
                                              acc[mt][nt][1] * d0);
                *(__half2*)&g_A[(size_t)r0 * D + col] = h;
            }
            if (r1 < n) {
                __half2 h = __floats2half2_rn(acc[mt][nt][2] * d1,
                                              acc[mt][nt][3] * d1);
                *(__half2*)&g_A[(size_t)r1 * D + col] = h;
            }
        }
    }
}

#define GEMM_SMEM (4 * 128 * SP * (int)sizeof(__half))

// ---------------------------------------------------------------------------
// Shared gather helper: accumulate fp16 row of g_A into fp32 acc[4].
// Lane l covers cols l*4 .. l*4+3 (8 bytes).
// ---------------------------------------------------------------------------
__device__ __forceinline__ void gather_row(float* acc, int row, int lane) {
    uint2 u = *(const uint2*)&g_A[(size_t)row * D + lane * 4];
    float2 a = __half22float2(*(__half2*)&u.x);
    float2 b = __half22float2(*(__half2*)&u.y);
    acc[0] += a.x; acc[1] += a.y; acc[2] += b.x; acc[3] += b.y;
}

// ---------------------------------------------------------------------------
// agg1: warp per node, no atomics, fused BN+ReLU.
// g_C[d] = relu( bn_s * ((g_A[d] + sum g_A[s]) * dinv[d]) + bn_t )
// ---------------------------------------------------------------------------
__global__ __launch_bounds__(256) void agg1(int n) {
    __shared__ float s_s[D], s_t[D];
    if (threadIdx.x < D) {
        s_s[threadIdx.x] = g_bn_s[threadIdx.x];
        s_t[threadIdx.x] = g_bn_t[threadIdx.x];
    }
    __syncthreads();

    int idx  = blockIdx.x * blockDim.x + threadIdx.x;
    int node = idx >> 5;
    int lane = idx & 31;
    if (node >= n) return;

    int beg = g_off[node];
    int cnt = g_cnt[node];

    float acc[4] = {0.f, 0.f, 0.f, 0.f};
    gather_row(acc, node, lane);   // self-loop

    int j = 0;
    for (; j + 2 <= cnt; j += 2) {
        int s0 = g_es[beg + j];
        int s1 = g_es[beg + j + 1];
        gather_row(acc, s0, lane);
        gather_row(acc, s1, lane);
    }
    if (j < cnt) gather_row(acc, g_es[beg + j], lane);

    float di = g_dinv[node];
    int col = lane * 4;
    float4 r;
    r.x = fmaxf(acc[0] * di * s_s[col]     + s_t[col],     0.f);
    r.y = fmaxf(acc[1] * di * s_s[col + 1] + s_t[col + 1], 0.f);
    r.z = fmaxf(acc[2] * di * s_s[col + 2] + s_t[col + 2], 0.f);
    r.w = fmaxf(acc[3] * di * s_s[col + 3] + s_t[col + 3], 0.f);
    *(float4*)&g_C[(size_t)node * D + col] = r;
}

// ---------------------------------------------------------------------------
// agg2 + final fused: warp per node (grid-stride), no atomics.
// h2 = (g_A[d] + sum g_A[s]) * dinv[d] + b2 ; jk = max(g_C[d], h2)
// logits = jk @ Wf + bf ; out = log_softmax(logits)
// ---------------------------------------------------------------------------
__global__ __launch_bounds__(256) void agg2_final(const float* __restrict__ b2,
                                                  const float* __restrict__ Wf,
                                                  const float* __restrict__ bf,
                                                  float* __restrict__ out,
                                                  int n) {
    __shared__ float Wfs[D][64];
    __shared__ float bfs[64];

    for (int i = threadIdx.x; i < D * 64; i += blockDim.x) {
        int r = i >> 6, c = i & 63;
        Wfs[r][c] = (c < DOUT) ? Wf[r * DOUT + c] : 0.0f;
    }
    if (threadIdx.x < 64)
        bfs[threadIdx.x] = (threadIdx.x < DOUT) ? bf[threadIdx.x] : 0.0f;
    __syncthreads();

    int lane = threadIdx.x & 31;
    int wid  = threadIdx.x >> 5;
    int wpb  = blockDim.x >> 5;

    float4 bb = *(const float4*)&b2[lane * 4];

    for (int node = blockIdx.x * wpb + wid; node < n; node += gridDim.x * wpb) {
        int beg = g_off[node];
        int cnt = g_cnt[node];

        float acc[4] = {0.f, 0.f, 0.f, 0.f};
        gather_row(acc, node, lane);   // self-loop

        int j = 0;
        for (; j + 2 <= cnt; j += 2) {
            int s0 = g_es[beg + j];
            int s1 = g_es[beg + j + 1];
            gather_row(acc, s0, lane);
            gather_row(acc, s1, lane);
        }
        if (j < cnt) gather_row(acc, g_es[beg + j], lane);

        float di = g_dinv[node];
        float4 h1 = *(const float4*)&g_C[(size_t)node * D + lane * 4];
        float jk[4];
        jk[0] = fmaxf(h1.x, acc[0] * di + bb.x);
        jk[1] = fmaxf(h1.y, acc[1] * di + bb.y);
        jk[2] = fmaxf(h1.z, acc[2] * di + bb.z);
        jk[3] = fmaxf(h1.w, acc[3] * di + bb.w);

        float acc0 = 0.f, acc1 = 0.f;
#pragma unroll
        for (int k = 0; k < D; k++) {
            float v = __shfl_sync(0xFFFFFFFFu, jk[k & 3], k >> 2);
            acc0 += v * Wfs[k][lane];
            acc1 += v * Wfs[k][lane + 32];
        }
        acc0 += bfs[lane];
        acc1 += bfs[lane + 32];

        bool v0 = (lane < DOUT);
        bool v1 = (lane + 32 < DOUT);
        float m = fmaxf(v0 ? acc0 : -CUDART_INF_F, v1 ? acc1 : -CUDART_INF_F);
#pragma unroll
        for (int o = 16; o; o >>= 1) m = fmaxf(m, __shfl_xor_sync(0xFFFFFFFFu, m, o));
        float se = (v0 ? expf(acc0 - m) : 0.f) + (v1 ? expf(acc1 - m) : 0.f);
#pragma unroll
        for (int o = 16; o; o >>= 1) se += __shfl_xor_sync(0xFFFFFFFFu, se, o);
        float lse = m + logf(se);

        if (v0) out[(size_t)node * DOUT + lane] = acc0 - lse;
        if (v1) out[(size_t)node * DOUT + lane + 32] = acc1 - lse;
    }
}

// ---------------------------------------------------------------------------
// Launch
// ---------------------------------------------------------------------------
extern "C" void kernel_launch(void* const* d_in, const int* in_sizes, int n_in,
                              void* d_out, int out_size) {
    const float* x     = (const float*)d_in[0];
    const void*  ei    = d_in[1];
    const float* W1    = (const float*)d_in[2];
    const float* b1    = (const float*)d_in[3];
    const float* gamma = (const float*)d_in[4];
    const float* beta  = (const float*)d_in[5];
    const float* mean  = (const float*)d_in[6];
    const float* var   = (const float*)d_in[7];
    const float* W2    = (const float*)d_in[8];
    const float* b2    = (const float*)d_in[9];
    const float* Wf    = (const float*)d_in[10];
    const float* bf    = (const float*)d_in[11];
    float* out = (float*)d_out;

    int n = in_sizes[0] / D;
    int e = in_sizes[1] / 2;

    static bool attr_set = false;
    if (!attr_set) {
        cudaFuncSetAttribute(gemm_mma, cudaFuncAttributeMaxDynamicSharedMemorySize,
                             GEMM_SMEM);
        attr_set = true;
    }

    // Dtype detection + counting sort by dst + degrees + BN prep
    detect_dtype<<<1, 32>>>((const unsigned int*)ei, e);
    cnt_zero<<<(n + 255) / 256, 256>>>(n);
    cnt_count<<<(e + 255) / 256, 256>>>(ei, e);
    int nb = (n + 2047) / 2048;
    scan1<<<nb, 256>>>(n);
    scan2<<<1, 32>>>(nb);
    scan3<<<(n + 255) / 256, 256>>>(n);
    scatter<<<(e + 255) / 256, 256>>>(ei, e);
    bn_prep<<<1, 128>>>(b1, gamma, beta, mean, var);

    int gemm_grid = (n + 127) / 128;
    int agg_grid  = (n * 32 + 255) / 256;   // warp per node, exact

    // Layer 1: tensor-core GEMM -> aggregation fused with BN+ReLU
    gemm_mma<<<gemm_grid, 256, GEMM_SMEM>>>(x, W1, 0, n);
    agg1<<<agg_grid, 256>>>(n);

    // Layer 2: tensor-core GEMM -> aggregation fused with JK+classifier+softmax
    gemm_mma<<<gemm_grid, 256, GEMM_SMEM>>>(nullptr, W2, 1, n);
    agg2_final<<<1036, 256>>>(b2, Wf, bf, out, n);
}

// round 8
// speedup vs baseline: 1.2318x; 1.2318x over previous
#include <cuda_runtime.h>
#include <cuda_fp16.h>
#include <math_constants.h>
#include <cstdint>

// Problem constants
#define MAXN 100000
#define MAXE 1600000
#define D 128
#define DOUT 47
#define BN_EPS 1e-5f

// Scratch (device globals; allocation-free per harness rules)
__device__ __half g_A[(size_t)MAXN * D];   // GEMM output (dinv-prescaled), fp16
__device__ __half g_Ch[(size_t)MAXN * D];  // h1 (post BN+ReLU), fp16
__device__ float  g_dinv[MAXN];            // 1/sqrt(deg)
__device__ float  g_bn_s[D];               // fused BN scale
__device__ float  g_bn_t[D];               // fused BN bias
__device__ int    g_cnt[MAXN];             // dst histogram (edges only)
__device__ int    g_off[MAXN];             // exclusive prefix of g_cnt
__device__ int    g_cursor[MAXN];          // scatter cursors
__device__ int    g_es[MAXE];              // src ids, sorted by dst
__device__ int    g_bsum[64];              // scan block sums
__device__ int    g_is64;                  // edge_index dtype flag

// ---------------------------------------------------------------------------
// cnt_zero + edge-index dtype detection fused (block 0 / thread 0 detects).
// int64 little-endian with values < 2^31 -> every odd 32-bit word is 0.
// ---------------------------------------------------------------------------
__global__ void cnt_zero_detect(const unsigned int* __restrict__ ei32, int e, int n) {
    int i = blockIdx.x * blockDim.x + threadIdx.x;
    if (i < n) g_cnt[i] = 0;
    if (blockIdx.x == 0 && threadIdx.x == 0) {
        int is64 = 1;
        int lim = (e < 64) ? e : 64;
        for (int k = 0; k < lim; k++) {
            if (ei32[2 * k + 1] != 0u) { is64 = 0; break; }
        }
        g_is64 = is64;
    }
}

__device__ __forceinline__ int load_idx(const void* __restrict__ ei, int e,
                                        int which, int i) {
    if (g_is64) {
        const long long* p = (const long long*)ei;
        return (int)p[(size_t)which * e + i];
    } else {
        const int* p = (const int*)ei;
        return p[(size_t)which * e + i];
    }
}

// ---------------------------------------------------------------------------
// Counting sort by dst: histogram -> scan -> scatter ; degrees ; BN prep
// ---------------------------------------------------------------------------
__global__ void cnt_count(const void* __restrict__ ei, int e) {
    int i = blockIdx.x * blockDim.x + threadIdx.x;
    if (i < e) atomicAdd(&g_cnt[load_idx(ei, e, 1, i)], 1);
}

__global__ __launch_bounds__(256) void scan1(int n) {
    __shared__ int warp_sums[8];
    int tid = threadIdx.x;
    int base = blockIdx.x * 2048 + tid * 8;
    int v[8];
    int tot = 0;
#pragma unroll
    for (int i = 0; i < 8; i++) {
        int idx = base + i;
        v[i] = (idx < n) ? g_cnt[idx] : 0;
        tot += v[i];
    }
    int lane = tid & 31, wid = tid >> 5;
    int x = tot;
#pragma unroll
    for (int o = 1; o < 32; o <<= 1) {
        int y = __shfl_up_sync(0xFFFFFFFFu, x, o);
        if (lane >= o) x += y;
    }
    if (lane == 31) warp_sums[wid] = x;
    __syncthreads();
    if (wid == 0) {
        int w = (lane < 8) ? warp_sums[lane] : 0;
#pragma unroll
        for (int o = 1; o < 8; o <<= 1) {
            int y = __shfl_up_sync(0xFFFFFFFFu, w, o);
            if (lane >= o && lane < 8) w += y;
        }
        if (lane < 8) warp_sums[lane] = w;
    }
    __syncthreads();
    int excl = x - tot + ((wid > 0) ? warp_sums[wid - 1] : 0);
    int run = excl;
#pragma unroll
    for (int i = 0; i < 8; i++) {
        int idx = base + i;
        if (idx < n) g_off[idx] = run;
        run += v[i];
    }
    if (tid == 255) g_bsum[blockIdx.x] = excl + tot;
}

__global__ void scan2(int nb) {
    if (threadIdx.x == 0 && blockIdx.x == 0) {
        int run = 0;
        for (int i = 0; i < nb; i++) {
            int t = g_bsum[i];
            g_bsum[i] = run;
            run += t;
        }
    }
}

__global__ void scan3(int n) {
    int i = blockIdx.x * blockDim.x + threadIdx.x;
    if (i < n) {
        int o = g_off[i] + g_bsum[i >> 11];
        g_off[i]    = o;
        g_cursor[i] = o;
        g_dinv[i]   = rsqrtf((float)(g_cnt[i] + 1));   // +1 self-loop
    }
}

__global__ void scatter(const void* __restrict__ ei, int e) {
    int i = blockIdx.x * blockDim.x + threadIdx.x;
    if (i < e) {
        int s = load_idx(ei, e, 0, i);
        int d = load_idx(ei, e, 1, i);
        int p = atomicAdd(&g_cursor[d], 1);
        g_es[p] = s;
    }
}

__global__ void bn_prep(const float* __restrict__ b1, const float* __restrict__ gamma,
                        const float* __restrict__ beta, const float* __restrict__ mean,
                        const float* __restrict__ var) {
    int i = threadIdx.x;
    if (i < D) {
        float rs = rsqrtf(var[i] + BN_EPS);
        float s = rs * gamma[i];
        g_bn_s[i] = s;
        g_bn_t[i] = (b1[i] - mean[i]) * s + beta[i];
    }
}

// ---------------------------------------------------------------------------
// SIMT GEMM (FFMA roofline-bound; proven optimal for this harness):
// g_A = fp16((X @ W) * dinv[row]).
// layer==0: X = x_in (fp32) ; layer==1: X = g_Ch (fp16).
// BM=64, BN=128, BK=32; 256 threads; 8x4 micro-tile per thread.
// ---------------------------------------------------------------------------
#define BM 64
#define BK 32

__global__ __launch_bounds__(256) void gemm128(const float* __restrict__ x_in,
                                               const float* __restrict__ W,
                                               int layer, int n) {
    __shared__ float As[BK][BM + 4];   // transposed x tile, padded
    __shared__ float Bs[BK][D];

    int tid = threadIdx.x;
    int tx = tid & 31;   // column group (4 cols each)
    int ty = tid >> 5;   // row group (8 rows each)
    int blockM = blockIdx.x * BM;

    float acc[8][4];
#pragma unroll
    for (int i = 0; i < 8; i++)
#pragma unroll
        for (int j = 0; j < 4; j++) acc[i][j] = 0.0f;

    for (int k0 = 0; k0 < D; k0 += BK) {
        // Load X tile 64x32 (transposed into As[k][m])
#pragma unroll
        for (int r = 0; r < 2; r++) {
            int i   = tid + 256 * r;      // 4-col chunk index, 8 per row
            int row = i >> 3;
            int c4  = i & 7;
            float4 v = make_float4(0.f, 0.f, 0.f, 0.f);
            int gr = blockM + row;
            if (gr < n) {
                if (layer == 0) {
                    v = *(const float4*)&x_in[(size_t)gr * D + k0 + c4 * 4];
                } else {
                    uint2 u = *(const uint2*)&g_Ch[(size_t)gr * D + k0 + c4 * 4];
                    float2 a = __half22float2(*(__half2*)&u.x);
                    float2 b = __half22float2(*(__half2*)&u.y);
                    v.x = a.x; v.y = a.y; v.z = b.x; v.w = b.y;
                }
            }
            As[c4 * 4 + 0][row] = v.x;
            As[c4 * 4 + 1][row] = v.y;
            As[c4 * 4 + 2][row] = v.z;
            As[c4 * 4 + 3][row] = v.w;
        }
        // Load W tile 32x128
#pragma unroll
        for (int r = 0; r < 4; r++) {
            int i   = tid + 256 * r;
            int row = i >> 5;
            int c4  = i & 31;
            *(float4*)&Bs[row][c4 * 4] =
                *(const float4*)&W[(size_t)(k0 + row) * D + c4 * 4];
        }
        __syncthreads();

#pragma unroll
        for (int k = 0; k < BK; k++) {
            float a[8];
            *(float4*)&a[0] = *(float4*)&As[k][ty * 8];
            *(float4*)&a[4] = *(float4*)&As[k][ty * 8 + 4];
            float4 b = *(float4*)&Bs[k][tx * 4];
#pragma unroll
            for (int i = 0; i < 8; i++) {
                acc[i][0] += a[i] * b.x;
                acc[i][1] += a[i] * b.y;
                acc[i][2] += a[i] * b.z;
                acc[i][3] += a[i] * b.w;
            }
        }
        __syncthreads();
    }

#pragma unroll
    for (int i = 0; i < 8; i++) {
        int row = blockM + ty * 8 + i;
        if (row < n) {
            float di = g_dinv[row];
            __half2 h0 = __floats2half2_rn(acc[i][0] * di, acc[i][1] * di);
            __half2 h1 = __floats2half2_rn(acc[i][2] * di, acc[i][3] * di);
            uint2 u;
            u.x = *(uint32_t*)&h0;
            u.y = *(uint32_t*)&h1;
            *(uint2*)&g_A[(size_t)row * D + tx * 4] = u;
        }
    }
}

// ---------------------------------------------------------------------------
// Gather helper: 16 lanes per row, uint4 = 8 halves (16B) per lane.
// Lane group hl (0..15) covers cols hl*8 .. hl*8+7 into acc[8].
// ---------------------------------------------------------------------------
__device__ __forceinline__ void gather8(float* acc, int row, int hl) {
    uint4 u = *(const uint4*)&g_A[(size_t)row * D + hl * 8];
    float2 a = __half22float2(*(__half2*)&u.x);
    float2 b = __half22float2(*(__half2*)&u.y);
    float2 c = __half22float2(*(__half2*)&u.z);
    float2 d = __half22float2(*(__half2*)&u.w);
    acc[0] += a.x; acc[1] += a.y; acc[2] += b.x; acc[3] += b.y;
    acc[4] += c.x; acc[5] += c.y; acc[6] += d.x; acc[7] += d.y;
}

// Warp-cooperative segmented sum over one node's edge list.
// Two edges processed concurrently (one per warp half), unrolled x2.
// On return: lanes 0-15 hold the combined sums; half-1 lanes hold garbage.
__device__ __forceinline__ void agg_node(float* acc, int node, int beg, int cnt,
                                         int half, int hl) {
    if (half == 0) gather8(acc, node, hl);   // self-loop

    int j = half;
    for (; j + 2 < cnt; j += 4) {            // handles j and j+2 for this half
        int s0 = g_es[beg + j];
        int s1 = g_es[beg + j + 2];
        gather8(acc, s0, hl);
        gather8(acc, s1, hl);
    }
    for (; j < cnt; j += 2) gather8(acc, g_es[beg + j], hl);

#pragma unroll
    for (int t = 0; t < 8; t++)
        acc[t] += __shfl_xor_sync(0xFFFFFFFFu, acc[t], 16);
}

// ---------------------------------------------------------------------------
// agg1: warp per node, fused BN+ReLU, fp16 output.
// g_Ch[d] = fp16(relu( bn_s * ((g_A[d] + sum g_A[s]) * dinv[d]) + bn_t ))
// ---------------------------------------------------------------------------
__global__ __launch_bounds__(256) void agg1(int n) {
    __shared__ float s_s[D], s_t[D];
    if (threadIdx.x < D) {
        s_s[threadIdx.x] = g_bn_s[threadIdx.x];
        s_t[threadIdx.x] = g_bn_t[threadIdx.x];
    }
    __syncthreads();

    int idx  = blockIdx.x * blockDim.x + threadIdx.x;
    int node = idx >> 5;
    int lane = idx & 31;
    if (node >= n) return;
    int half = lane >> 4;
    int hl   = lane & 15;

    float acc[8] = {0.f, 0.f, 0.f, 0.f, 0.f, 0.f, 0.f, 0.f};
    agg_node(acc, node, g_off[node], g_cnt[node], half, hl);

    if (half == 0) {
        float di = g_dinv[node];
        int col = hl * 8;
        __half2 h[4];
#pragma unroll
        for (int t = 0; t < 4; t++) {
            float r0 = fmaxf(acc[2*t]   * di * s_s[col + 2*t]   + s_t[col + 2*t],   0.f);
            float r1 = fmaxf(acc[2*t+1] * di * s_s[col + 2*t+1] + s_t[col + 2*t+1], 0.f);
            h[t] = __floats2half2_rn(r0, r1);
        }
        uint4 u;
        u.x = *(uint32_t*)&h[0]; u.y = *(uint32_t*)&h[1];
        u.z = *(uint32_t*)&h[2]; u.w = *(uint32_t*)&h[3];
        *(uint4*)&g_Ch[(size_t)node * D + col] = u;
    }
}

// ---------------------------------------------------------------------------
// agg2 + final fused: warp per node (grid-stride).
// h2 = (g_A[d] + sum g_A[s]) * dinv[d] + b2 ; jk = max(g_Ch[d], h2)
// logits = jk @ Wf + bf ; out = log_softmax(logits)
// ---------------------------------------------------------------------------
__global__ __launch_bounds__(256) void agg2_final(const float* __restrict__ b2,
                                                  const float* __restrict__ Wf,
                                                  const float* __restrict__ bf,
                                                  float* __restrict__ out,
                                                  int n) {
    __shared__ float Wfs[D][64];
    __shared__ float bfs[64];

    for (int i = threadIdx.x; i < D * 64; i += blockDim.x) {
        int r = i >> 6, c = i & 63;
        Wfs[r][c] = (c < DOUT) ? Wf[r * DOUT + c] : 0.0f;
    }
    if (threadIdx.x < 64)
        bfs[threadIdx.x] = (threadIdx.x < DOUT) ? bf[threadIdx.x] : 0.0f;
    __syncthreads();

    int lane = threadIdx.x & 31;
    int wid  = threadIdx.x >> 5;
    int wpb  = blockDim.x >> 5;
    int half = lane >> 4;
    int hl   = lane & 15;

    // b2 slice for this lane group (used only by half 0 after combine)
    float4 bb0 = *(const float4*)&b2[hl * 8];
    float4 bb1 = *(const float4*)&b2[hl * 8 + 4];
    float bbv[8] = {bb0.x, bb0.y, bb0.z, bb0.w, bb1.x, bb1.y, bb1.z, bb1.w};

    for (int node = blockIdx.x * wpb + wid; node < n; node += gridDim.x * wpb) {
        float acc[8] = {0.f, 0.f, 0.f, 0.f, 0.f, 0.f, 0.f, 0.f};
        agg_node(acc, node, g_off[node], g_cnt[node], half, hl);

        float jk[8];
        if (half == 0) {
            float di = g_dinv[node];
            uint4 u = *(const uint4*)&g_Ch[(size_t)node * D + hl * 8];
            float2 a = __half22float2(*(__half2*)&u.x);
            float2 b = __half22float2(*(__half2*)&u.y);
            float2 c = __half22float2(*(__half2*)&u.z);
            float2 d = __half22float2(*(__half2*)&u.w);
            float h1v[8] = {a.x, a.y, b.x, b.y, c.x, c.y, d.x, d.y};
#pragma unroll
            for (int t = 0; t < 8; t++)
                jk[t] = fmaxf(h1v[t], acc[t] * di + bbv[t]);
        } else {
#pragma unroll
            for (int t = 0; t < 8; t++) jk[t] = 0.f;   // never sourced
        }

        float acc0 = 0.f, acc1 = 0.f;
#pragma unroll
        for (int k = 0; k < D; k++) {
            float v = __shfl_sync(0xFFFFFFFFu, jk[k & 7], k >> 3);
            acc0 += v * Wfs[k][lane];
            acc1 += v * Wfs[k][lane + 32];
        }
        acc0 += bfs[lane];
        acc1 += bfs[lane + 32];

        bool v0 = (lane < DOUT);
        bool v1 = (lane + 32 < DOUT);
        float m = fmaxf(v0 ? acc0 : -CUDART_INF_F, v1 ? acc1 : -CUDART_INF_F);
#pragma unroll
        for (int o = 16; o; o >>= 1) m = fmaxf(m, __shfl_xor_sync(0xFFFFFFFFu, m, o));
        float se = (v0 ? expf(acc0 - m) : 0.f) + (v1 ? expf(acc1 - m) : 0.f);
#pragma unroll
        for (int o = 16; o; o >>= 1) se += __shfl_xor_sync(0xFFFFFFFFu, se, o);
        float lse = m + logf(se);

        if (v0) out[(size_t)node * DOUT + lane] = acc0 - lse;
        if (v1) out[(size_t)node * DOUT + lane + 32] = acc1 - lse;
    }
}

// ---------------------------------------------------------------------------
// Launch
// ---------------------------------------------------------------------------
extern "C" void kernel_launch(void* const* d_in, const int* in_sizes, int n_in,
                              void* d_out, int out_size) {
    const float* x     = (const float*)d_in[0];
    const void*  ei    = d_in[1];
    const float* W1    = (const float*)d_in[2];
    const float* b1    = (const float*)d_in[3];
    const float* gamma = (const float*)d_in[4];
    const float* beta  = (const float*)d_in[5];
    const float* mean  = (const float*)d_in[6];
    const float* var   = (const float*)d_in[7];
    const float* W2    = (const float*)d_in[8];
    const float* b2    = (const float*)d_in[9];
    const float* Wf    = (const float*)d_in[10];
    const float* bf    = (const float*)d_in[11];
    float* out = (float*)d_out;

    int n = in_sizes[0] / D;
    int e = in_sizes[1] / 2;

    // Dtype detection + counting sort by dst + degrees + BN prep
    cnt_zero_detect<<<(n + 255) / 256, 256>>>((const unsigned int*)ei, e, n);
    cnt_count<<<(e + 255) / 256, 256>>>(ei, e);
    int nb = (n + 2047) / 2048;
    scan1<<<nb, 256>>>(n);
    scan2<<<1, 32>>>(nb);
    scan3<<<(n + 255) / 256, 256>>>(n);
    scatter<<<(e + 255) / 256, 256>>>(ei, e);
    bn_prep<<<1, 128>>>(b1, gamma, beta, mean, var);

    int gemm_grid = (n + BM - 1) / BM;
    int agg_grid  = (n * 32 + 255) / 256;   // warp per node

    // Layer 1: GEMM -> aggregation fused with BN+ReLU
    gemm128<<<gemm_grid, 256>>>(x, W1, 0, n);
    agg1<<<agg_grid, 256>>>(n);

    // Layer 2: GEMM -> aggregation fused with JK max + classifier + log_softmax
    gemm128<<<gemm_grid, 256>>>(nullptr, W2, 1, n);
    agg2_final<<<1036, 256>>>(b2, Wf, bf, out, n);
}

// round 9
// speedup vs baseline: 1.2329x; 1.0009x over previous
#include <cuda_runtime.h>
#include <cuda_fp16.h>
#include <math_constants.h>
#include <cstdint>

// Problem constants
#define MAXN 100000
#define MAXE 1600000
#define D 128
#define DOUT 47
#define BN_EPS 1e-5f

// Scratch (device globals; allocation-free per harness rules)
__device__ __half g_A[(size_t)MAXN * D];   // GEMM output (unscaled), fp16
__device__ __half g_Ch[(size_t)MAXN * D];  // h1 (post BN+ReLU), fp16
__device__ float  g_dinv[MAXN];            // 1/sqrt(deg)
__device__ float  g_bn_s[D];               // fused BN scale
__device__ float  g_bn_t[D];               // fused BN bias
__device__ int    g_cnt[MAXN];             // dst histogram (edges only)
__device__ int    g_off[MAXN];             // exclusive prefix of g_cnt
__device__ int    g_cursor[MAXN];          // scatter cursors
__device__ int    g_es[MAXE];              // src ids, sorted by dst
__device__ int    g_bsum[64];              // scan block sums
__device__ int    g_is64;                  // edge_index dtype flag

// ---------------------------------------------------------------------------
// cnt_zero + edge-index dtype detection fused.
// int64 little-endian with values < 2^31 -> every odd 32-bit word is 0.
// ---------------------------------------------------------------------------
__global__ void cnt_zero_detect(const unsigned int* __restrict__ ei32, int e, int n) {
    int i = blockIdx.x * blockDim.x + threadIdx.x;
    if (i < n) g_cnt[i] = 0;
    if (blockIdx.x == 0 && threadIdx.x == 0) {
        int is64 = 1;
        int lim = (e < 64) ? e : 64;
        for (int k = 0; k < lim; k++) {
            if (ei32[2 * k + 1] != 0u) { is64 = 0; break; }
        }
        g_is64 = is64;
    }
}

__device__ __forceinline__ int load_idx(const void* __restrict__ ei, int e,
                                        int which, int i) {
    if (g_is64) {
        const long long* p = (const long long*)ei;
        return (int)p[(size_t)which * e + i];
    } else {
        const int* p = (const int*)ei;
        return p[(size_t)which * e + i];
    }
}

// ---------------------------------------------------------------------------
// Counting sort by dst: histogram -> scan -> scatter ; degrees ; BN prep
// ---------------------------------------------------------------------------
__global__ void cnt_count(const void* __restrict__ ei, int e) {
    int i = blockIdx.x * blockDim.x + threadIdx.x;
    if (i < e) atomicAdd(&g_cnt[load_idx(ei, e, 1, i)], 1);
}

__global__ __launch_bounds__(256) void scan1(int n) {
    __shared__ int warp_sums[8];
    int tid = threadIdx.x;
    int base = blockIdx.x * 2048 + tid * 8;
    int v[8];
    int tot = 0;
#pragma unroll
    for (int i = 0; i < 8; i++) {
        int idx = base + i;
        v[i] = (idx < n) ? g_cnt[idx] : 0;
        tot += v[i];
    }
    int lane = tid & 31, wid = tid >> 5;
    int x = tot;
#pragma unroll
    for (int o = 1; o < 32; o <<= 1) {
        int y = __shfl_up_sync(0xFFFFFFFFu, x, o);
        if (lane >= o) x += y;
    }
    if (lane == 31) warp_sums[wid] = x;
    __syncthreads();
    if (wid == 0) {
        int w = (lane < 8) ? warp_sums[lane] : 0;
#pragma unroll
        for (int o = 1; o < 8; o <<= 1) {
            int y = __shfl_up_sync(0xFFFFFFFFu, w, o);
            if (lane >= o && lane < 8) w += y;
        }
        if (lane < 8) warp_sums[lane] = w;
    }
    __syncthreads();
    int excl = x - tot + ((wid > 0) ? warp_sums[wid - 1] : 0);
    int run = excl;
#pragma unroll
    for (int i = 0; i < 8; i++) {
        int idx = base + i;
        if (idx < n) g_off[idx] = run;
        run += v[i];
    }
    if (tid == 255) g_bsum[blockIdx.x] = excl + tot;
}

__global__ void scan2(int nb) {
    if (threadIdx.x == 0 && blockIdx.x == 0) {
        int run = 0;
        for (int i = 0; i < nb; i++) {
            int t = g_bsum[i];
            g_bsum[i] = run;
            run += t;
        }
    }
}

__global__ void scan3(int n) {
    int i = blockIdx.x * blockDim.x + threadIdx.x;
    if (i < n) {
        int o = g_off[i] + g_bsum[i >> 11];
        g_off[i]    = o;
        g_cursor[i] = o;
        g_dinv[i]   = rsqrtf((float)(g_cnt[i] + 1));   // +1 self-loop
    }
}

__global__ void scatter(const void* __restrict__ ei, int e) {
    int i = blockIdx.x * blockDim.x + threadIdx.x;
    if (i < e) {
        int s = load_idx(ei, e, 0, i);
        int d = load_idx(ei, e, 1, i);
        int p = atomicAdd(&g_cursor[d], 1);
        g_es[p] = s;
    }
}

__global__ void bn_prep(const float* __restrict__ b1, const float* __restrict__ gamma,
                        const float* __restrict__ beta, const float* __restrict__ mean,
                        const float* __restrict__ var) {
    int i = threadIdx.x;
    if (i < D) {
        float rs = rsqrtf(var[i] + BN_EPS);
        float s = rs * gamma[i];
        g_bn_s[i] = s;
        g_bn_t[i] = (b1[i] - mean[i]) * s + beta[i];
    }
}

// ---------------------------------------------------------------------------
// SIMT GEMM (FFMA roofline-bound): g_A = fp16(X @ W)  -- NO dinv dependency.
// layer==0: X = x_in (fp32) ; layer==1: X = g_Ch (fp16).
// BM=64, BN=128, BK=32; 256 threads; 8x4 micro-tile per thread.
// ---------------------------------------------------------------------------
#define BM 64
#define BK 32

__global__ __launch_bounds__(256) void gemm128(const float* __restrict__ x_in,
                                               const float* __restrict__ W,
                                               int layer, int n) {
    __shared__ float As[BK][BM + 4];   // transposed x tile, padded
    __shared__ float Bs[BK][D];

    int tid = threadIdx.x;
    int tx = tid & 31;   // column group (4 cols each)
    int ty = tid >> 5;   // row group (8 rows each)
    int blockM = blockIdx.x * BM;

    float acc[8][4];
#pragma unroll
    for (int i = 0; i < 8; i++)
#pragma unroll
        for (int j = 0; j < 4; j++) acc[i][j] = 0.0f;

    for (int k0 = 0; k0 < D; k0 += BK) {
#pragma unroll
        for (int r = 0; r < 2; r++) {
            int i   = tid + 256 * r;
            int row = i >> 3;
            int c4  = i & 7;
            float4 v = make_float4(0.f, 0.f, 0.f, 0.f);
            int gr = blockM + row;
            if (gr < n) {
                if (layer == 0) {
                    v = *(const float4*)&x_in[(size_t)gr * D + k0 + c4 * 4];
                } else {
                    uint2 u = *(const uint2*)&g_Ch[(size_t)gr * D + k0 + c4 * 4];
                    float2 a = __half22float2(*(__half2*)&u.x);
                    float2 b = __half22float2(*(__half2*)&u.y);
                    v.x = a.x; v.y = a.y; v.z = b.x; v.w = b.y;
                }
            }
            As[c4 * 4 + 0][row] = v.x;
            As[c4 * 4 + 1][row] = v.y;
            As[c4 * 4 + 2][row] = v.z;
            As[c4 * 4 + 3][row] = v.w;
        }
#pragma unroll
        for (int r = 0; r < 4; r++) {
            int i   = tid + 256 * r;
            int row = i >> 5;
            int c4  = i & 31;
            *(float4*)&Bs[row][c4 * 4] =
                *(const float4*)&W[(size_t)(k0 + row) * D + c4 * 4];
        }
        __syncthreads();

#pragma unroll
        for (int k = 0; k < BK; k++) {
            float a[8];
            *(float4*)&a[0] = *(float4*)&As[k][ty * 8];
            *(float4*)&a[4] = *(float4*)&As[k][ty * 8 + 4];
            float4 b = *(float4*)&Bs[k][tx * 4];
#pragma unroll
            for (int i = 0; i < 8; i++) {
                acc[i][0] += a[i] * b.x;
                acc[i][1] += a[i] * b.y;
                acc[i][2] += a[i] * b.z;
                acc[i][3] += a[i] * b.w;
            }
        }
        __syncthreads();
    }

#pragma unroll
    for (int i = 0; i < 8; i++) {
        int row = blockM + ty * 8 + i;
        if (row < n) {
            __half2 h0 = __floats2half2_rn(acc[i][0], acc[i][1]);
            __half2 h1 = __floats2half2_rn(acc[i][2], acc[i][3]);
            uint2 u;
            u.x = *(uint32_t*)&h0;
            u.y = *(uint32_t*)&h1;
            *(uint2*)&g_A[(size_t)row * D + tx * 4] = u;
        }
    }
}

// ---------------------------------------------------------------------------
// Gather helper: 16 lanes per row, uint4 = 8 halves (16B) per lane,
// weighted by scalar w (= dinv[src]).
// ---------------------------------------------------------------------------
__device__ __forceinline__ void gather8w(float* acc, int row, int hl, float w) {
    uint4 u = *(const uint4*)&g_A[(size_t)row * D + hl * 8];
    float2 a = __half22float2(*(__half2*)&u.x);
    float2 b = __half22float2(*(__half2*)&u.y);
    float2 c = __half22float2(*(__half2*)&u.z);
    float2 d = __half22float2(*(__half2*)&u.w);
    acc[0] = fmaf(w, a.x, acc[0]); acc[1] = fmaf(w, a.y, acc[1]);
    acc[2] = fmaf(w, b.x, acc[2]); acc[3] = fmaf(w, b.y, acc[3]);
    acc[4] = fmaf(w, c.x, acc[4]); acc[5] = fmaf(w, c.y, acc[5]);
    acc[6] = fmaf(w, d.x, acc[6]); acc[7] = fmaf(w, d.y, acc[7]);
}

// Warp-cooperative segmented weighted sum. Two edges concurrently (one per
// warp half), unrolled x2. Lanes 0-15 hold combined sums on return.
__device__ __forceinline__ void agg_node(float* acc, int node, int beg, int cnt,
                                         int half, int hl, float dinv_d) {
    if (half == 0) gather8w(acc, node, hl, dinv_d);   // self-loop

    int j = half;
    for (; j + 2 < cnt; j += 4) {
        int s0 = g_es[beg + j];
        int s1 = g_es[beg + j + 2];
        float w0 = g_dinv[s0];
        float w1 = g_dinv[s1];
        gather8w(acc, s0, hl, w0);
        gather8w(acc, s1, hl, w1);
    }
    for (; j < cnt; j += 2) {
        int s0 = g_es[beg + j];
        gather8w(acc, s0, hl, g_dinv[s0]);
    }

#pragma unroll
    for (int t = 0; t < 8; t++)
        acc[t] += __shfl_xor_sync(0xFFFFFFFFu, acc[t], 16);
}

// ---------------------------------------------------------------------------
// agg1: warp per node, fused BN+ReLU, fp16 output.
// g_Ch[d] = fp16(relu( bn_s * (dinv[d]*(dinv[d]*row[d] + sum dinv[s]*row[s])) + bn_t ))
// ---------------------------------------------------------------------------
__global__ __launch_bounds__(256) void agg1(int n) {
    __shared__ float s_s[D], s_t[D];
    if (threadIdx.x < D) {
        s_s[threadIdx.x] = g_bn_s[threadIdx.x];
        s_t[threadIdx.x] = g_bn_t[threadIdx.x];
    }
    __syncthreads();

    int idx  = blockIdx.x * blockDim.x + threadIdx.x;
    int node = idx >> 5;
    int lane = idx & 31;
    if (node >= n) return;
    int half = lane >> 4;
    int hl   = lane & 15;

    float di = g_dinv[node];
    float acc[8] = {0.f, 0.f, 0.f, 0.f, 0.f, 0.f, 0.f, 0.f};
    agg_node(acc, node, g_off[node], g_cnt[node], half, hl, di);

    if (half == 0) {
        int col = hl * 8;
        __half2 h[4];
#pragma unroll
        for (int t = 0; t < 4; t++) {
            float r0 = fmaxf(acc[2*t]   * di * s_s[col + 2*t]   + s_t[col + 2*t],   0.f);
            float r1 = fmaxf(acc[2*t+1] * di * s_s[col + 2*t+1] + s_t[col + 2*t+1], 0.f);
            h[t] = __floats2half2_rn(r0, r1);
        }
        uint4 u;
        u.x = *(uint32_t*)&h[0]; u.y = *(uint32_t*)&h[1];
        u.z = *(uint32_t*)&h[2]; u.w = *(uint32_t*)&h[3];
        *(uint4*)&g_Ch[(size_t)node * D + col] = u;
    }
}

// ---------------------------------------------------------------------------
// agg2 + final fused: warp per node (grid-stride).
// h2 = dinv[d]*(dinv[d]*row[d] + sum dinv[s]*row[s]) + b2 ; jk = max(g_Ch[d], h2)
// logits = jk @ Wf + bf ; out = log_softmax(logits)
// ---------------------------------------------------------------------------
__global__ __launch_bounds__(256) void agg2_final(const float* __restrict__ b2,
                                                  const float* __restrict__ Wf,
                                                  const float* __restrict__ bf,
                                                  float* __restrict__ out,
                                                  int n) {
    __shared__ float Wfs[D][64];
    __shared__ float bfs[64];

    for (int i = threadIdx.x; i < D * 64; i += blockDim.x) {
        int r = i >> 6, c = i & 63;
        Wfs[r][c] = (c < DOUT) ? Wf[r * DOUT + c] : 0.0f;
    }
    if (threadIdx.x < 64)
        bfs[threadIdx.x] = (threadIdx.x < DOUT) ? bf[threadIdx.x] : 0.0f;
    __syncthreads();

    int lane = threadIdx.x & 31;
    int wid  = threadIdx.x >> 5;
    int wpb  = blockDim.x >> 5;
    int half = lane >> 4;
    int hl   = lane & 15;

    float4 bb0 = *(const float4*)&b2[hl * 8];
    float4 bb1 = *(const float4*)&b2[hl * 8 + 4];
    float bbv[8] = {bb0.x, bb0.y, bb0.z, bb0.w, bb1.x, bb1.y, bb1.z, bb1.w};

    for (int node = blockIdx.x * wpb + wid; node < n; node += gridDim.x * wpb) {
        float di = g_dinv[node];
        float acc[8] = {0.f, 0.f, 0.f, 0.f, 0.f, 0.f, 0.f, 0.f};
        agg_node(acc, node, g_off[node], g_cnt[node], half, hl, di);

        float jk[8];
        if (half == 0) {
            uint4 u = *(const uint4*)&g_Ch[(size_t)node * D + hl * 8];
            float2 a = __half22float2(*(__half2*)&u.x);
            float2 b = __half22float2(*(__half2*)&u.y);
            float2 c = __half22float2(*(__half2*)&u.z);
            float2 d = __half22float2(*(__half2*)&u.w);
            float h1v[8] = {a.x, a.y, b.x, b.y, c.x, c.y, d.x, d.y};
#pragma unroll
            for (int t = 0; t < 8; t++)
                jk[t] = fmaxf(h1v[t], acc[t] * di + bbv[t]);
        } else {
#pragma unroll
            for (int t = 0; t < 8; t++) jk[t] = 0.f;   // never sourced
        }

        float acc0 = 0.f, acc1 = 0.f;
#pragma unroll
        for (int k = 0; k < D; k++) {
            float v = __shfl_sync(0xFFFFFFFFu, jk[k & 7], k >> 3);
            acc0 += v * Wfs[k][lane];
            acc1 += v * Wfs[k][lane + 32];
        }
        acc0 += bfs[lane];
        acc1 += bfs[lane + 32];

        bool v0 = (lane < DOUT);
        bool v1 = (lane + 32 < DOUT);
        float m = fmaxf(v0 ? acc0 : -CUDART_INF_F, v1 ? acc1 : -CUDART_INF_F);
#pragma unroll
        for (int o = 16; o; o >>= 1) m = fmaxf(m, __shfl_xor_sync(0xFFFFFFFFu, m, o));
        float se = (v0 ? expf(acc0 - m) : 0.f) + (v1 ? expf(acc1 - m) : 0.f);
#pragma unroll
        for (int o = 16; o; o >>= 1) se += __shfl_xor_sync(0xFFFFFFFFu, se, o);
        float lse = m + logf(se);

        if (v0) out[(size_t)node * DOUT + lane] = acc0 - lse;
        if (v1) out[(size_t)node * DOUT + lane + 32] = acc1 - lse;
    }
}

// ---------------------------------------------------------------------------
// Launch: sort chain forked onto a side stream, overlapped with GEMM1.
// ---------------------------------------------------------------------------
extern "C" void kernel_launch(void* const* d_in, const int* in_sizes, int n_in,
                              void* d_out, int out_size) {
    const float* x     = (const float*)d_in[0];
    const void*  ei    = d_in[1];
    const float* W1    = (const float*)d_in[2];
    const float* b1    = (const float*)d_in[3];
    const float* gamma = (const float*)d_in[4];
    const float* beta  = (const float*)d_in[5];
    const float* mean  = (const float*)d_in[6];
    const float* var   = (const float*)d_in[7];
    const float* W2    = (const float*)d_in[8];
    const float* b2    = (const float*)d_in[9];
    const float* Wf    = (const float*)d_in[10];
    const float* bf    = (const float*)d_in[11];
    float* out = (float*)d_out;

    int n = in_sizes[0] / D;
    int e = in_sizes[1] / 2;

    static cudaStream_t s_side = nullptr;
    static cudaEvent_t  ev_fork = nullptr, ev_join = nullptr;
    if (!s_side) {
        cudaStreamCreateWithFlags(&s_side, cudaStreamNonBlocking);
        cudaEventCreateWithFlags(&ev_fork, cudaEventDisableTiming);
        cudaEventCreateWithFlags(&ev_join, cudaEventDisableTiming);
    }

    int gemm_grid = (n + BM - 1) / BM;
    int agg_grid  = (n * 32 + 255) / 256;   // warp per node
    int nb = (n + 2047) / 2048;

    // Fork: side stream runs the sort/degree/BN chain.
    cudaEventRecord(ev_fork, 0);
    cudaStreamWaitEvent(s_side, ev_fork, 0);

    cnt_zero_detect<<<(n + 255) / 256, 256, 0, s_side>>>((const unsigned int*)ei, e, n);
    cnt_count<<<(e + 255) / 256, 256, 0, s_side>>>(ei, e);
    scan1<<<nb, 256, 0, s_side>>>(n);
    scan2<<<1, 32, 0, s_side>>>(nb);
    scan3<<<(n + 255) / 256, 256, 0, s_side>>>(n);
    scatter<<<(e + 255) / 256, 256, 0, s_side>>>(ei, e);
    bn_prep<<<1, 128, 0, s_side>>>(b1, gamma, beta, mean, var);
    cudaEventRecord(ev_join, s_side);

    // Main stream: GEMM1 (independent of the sort chain).
    gemm128<<<gemm_grid, 256>>>(x, W1, 0, n);

    // Join, then the dependent tail.
    cudaStreamWaitEvent(0, ev_join, 0);
    agg1<<<agg_grid, 256>>>(n);
    gemm128<<<gemm_grid, 256>>>(nullptr, W2, 1, n);
    agg2_final<<<1036, 256>>>(b2, Wf, bf, out, n);
}